// round 6
// baseline (speedup 1.0000x reference)
#include <cuda_runtime.h>

// Problem constants (fixed: points shape (4, 8192, 3) fp32)
#define BATCH    4
#define NPTS     8192
#define NQ_TOT   (BATCH * NPTS)     // 32768
#define NN_SIZE  16
#define NK       17                  // 16 neighbors + self slot
#define RADIUS2  0.25f
#define EPS      1e-4f

// Spatial grid: cell width 0.5 (= radius), 19 cells/dim covering [-4.75, 4.75].
// Clamping is exact: |dx|<=0.5 => cell indices differ <=1, clamp is monotone.
#define GRIDC    19
#define NCELL    (GRIDC * GRIDC * GRIDC)   // 6859
#define ORIG     4.75f

#define CAP      448                 // per-thread within-radius buffer (worst ~350)

__device__ int    g_counts[BATCH * NCELL];
__device__ int    g_start [BATCH * (NCELL + 1)];   // exclusive offsets per batch
__device__ int    g_cursor[BATCH * NCELL];         // scatter cursors
__device__ float4 g_sorted[NQ_TOT];                // (x, y, z, |p|^2), cell-sorted per batch

__device__ __forceinline__ int cell_coord(float v) {
    int c = (int)floorf((v + ORIG) * 2.0f);
    return min(max(c, 0), GRIDC - 1);
}

// ---------------- Pass 0: zero counts + output ----------------
__global__ void init_kernel(float* out) {
    const int i = blockIdx.x * blockDim.x + threadIdx.x;
    if (i == 0) out[0] = 0.0f;
    for (int k = i; k < BATCH * NCELL; k += gridDim.x * blockDim.x)
        g_counts[k] = 0;
}

// ---------------- Pass 1: histogram ----------------
__global__ void __launch_bounds__(256)
hist_kernel(const float* __restrict__ pts) {
    const int i = blockIdx.x * blockDim.x + threadIdx.x;
    if (i >= NQ_TOT) return;
    const int b = i >> 13;
    const float x = pts[i * 3 + 0], y = pts[i * 3 + 1], z = pts[i * 3 + 2];
    const int cell = (cell_coord(z) * GRIDC + cell_coord(y)) * GRIDC + cell_coord(x);
    atomicAdd(&g_counts[b * NCELL + cell], 1);
}

// ---------------- Pass 2: per-batch exclusive scan (1 block/batch) ----------------
#define SCAN_T 1024
#define ITEMS  7                     // 1024*7 = 7168 >= 6859
__global__ void __launch_bounds__(SCAN_T)
scan_kernel() {
    const int b = blockIdx.x;
    const int t = threadIdx.x;
    __shared__ int sh[SCAN_T];

    int loc[ITEMS];
    int s = 0;
    const int base = t * ITEMS;
#pragma unroll
    for (int k = 0; k < ITEMS; ++k) {
        const int c = (base + k < NCELL) ? g_counts[b * NCELL + base + k] : 0;
        loc[k] = s;
        s += c;
    }
    sh[t] = s;
    __syncthreads();
    for (int off = 1; off < SCAN_T; off <<= 1) {
        const int v = (t >= off) ? sh[t - off] : 0;
        __syncthreads();
        sh[t] += v;
        __syncthreads();
    }
    const int excl = sh[t] - s;
#pragma unroll
    for (int k = 0; k < ITEMS; ++k) {
        if (base + k < NCELL) {
            const int o = excl + loc[k];
            g_start [b * (NCELL + 1) + base + k] = o;
            g_cursor[b * NCELL + base + k]       = o;
        }
    }
    if (t == SCAN_T - 1)
        g_start[b * (NCELL + 1) + NCELL] = sh[SCAN_T - 1];   // == NPTS
}

// ---------------- Pass 3: scatter into cell-sorted order ----------------
__global__ void __launch_bounds__(256)
scatter_kernel(const float* __restrict__ pts) {
    const int i = blockIdx.x * blockDim.x + threadIdx.x;
    if (i >= NQ_TOT) return;
    const int b = i >> 13;
    const float x = pts[i * 3 + 0], y = pts[i * 3 + 1], z = pts[i * 3 + 2];
    const int cell = (cell_coord(z) * GRIDC + cell_coord(y)) * GRIDC + cell_coord(x);
    const int pos  = atomicAdd(&g_cursor[b * NCELL + cell], 1);
    g_sorted[b * NPTS + pos] = make_float4(x, y, z, fmaf(x, x, fmaf(y, y, z * z)));
}

// ---------------- Pass 4: per-query 27-cell kNN + loss ----------------
#define BLOCK 128
__global__ void __launch_bounds__(BLOCK)
knn_kernel(float* __restrict__ out) {
    const int qidx = blockIdx.x * BLOCK + threadIdx.x;   // sorted-order query id
    const int b    = qidx >> 13;
    const int bs   = b * NPTS;
    const int goff = b * (NCELL + 1);

    const float4 q = g_sorted[qidx];
    const float qs  = q.w;
    const float m2x = -2.0f * q.x, m2y = -2.0f * q.y, m2z = -2.0f * q.z;
    const int cx = cell_coord(q.x), cy = cell_coord(q.y), cz = cell_coord(q.z);
    const int x0 = max(cx - 1, 0), x1 = min(cx + 1, GRIDC - 1);

    // Collect within-radius d^2 values (self included: d^2 ~ 0).
    float buf[CAP];
    int   cnt = 0;
#pragma unroll
    for (int dz = -1; dz <= 1; ++dz) {
        const int z = cz + dz;
        if ((unsigned)z >= GRIDC) continue;
#pragma unroll
        for (int dy = -1; dy <= 1; ++dy) {
            const int y = cy + dy;
            if ((unsigned)y >= GRIDC) continue;
            const int rowbase = (z * GRIDC + y) * GRIDC;
            const int js = g_start[goff + rowbase + x0];
            const int je = g_start[goff + rowbase + x1 + 1];
#pragma unroll 4
            for (int j = js; j < je; ++j) {
                const float4 c = g_sorted[bs + j];
                float t = qs + c.w;
                t = fmaf(m2x, c.x, t);
                t = fmaf(m2y, c.y, t);
                t = fmaf(m2z, c.z, t);
                if (t < RADIUS2) {
                    if (cnt < CAP) buf[cnt] = t;
                    ++cnt;
                }
            }
        }
    }
    if (cnt > CAP) cnt = CAP;

    // Capped sorted top-NK over the buffer (sentinel RADIUS2 -> f == 0).
    float a[NK];
#pragma unroll
    for (int k = 0; k < NK; ++k) a[k] = RADIUS2;
    for (int i = 0; i < cnt; ++i) {
        const float v = buf[i];
#pragma unroll
        for (int k = NK - 1; k > 0; --k)
            a[k] = (v < a[k]) ? fmaxf(v, a[k - 1]) : a[k];
        a[0] = fminf(a[0], v);
    }

    // Slot 0 is the query itself. Sum f over slots 1..16.
    float s = 0.0f;
#pragma unroll
    for (int k = 1; k < NK; ++k) {
        const float v = a[k];
        if (v < RADIUS2) s += rsqrtf(v + EPS);
    }
    s *= (1.0f / (float)(NQ_TOT * NN_SIZE));   // fold in the mean

    // Warp + block reduction -> atomicAdd
#pragma unroll
    for (int off = 16; off > 0; off >>= 1)
        s += __shfl_xor_sync(0xFFFFFFFFu, s, off);

    __shared__ float wsum[BLOCK / 32];
    const int lane = threadIdx.x & 31;
    const int wid  = threadIdx.x >> 5;
    if (lane == 0) wsum[wid] = s;
    __syncthreads();
    if (threadIdx.x == 0) {
        float t = 0.0f;
#pragma unroll
        for (int w = 0; w < BLOCK / 32; ++w) t += wsum[w];
        atomicAdd(out, t);
    }
}

extern "C" void kernel_launch(void* const* d_in, const int* in_sizes, int n_in,
                              void* d_out, int out_size) {
    const float* pts = (const float*)d_in[0];
    float* out = (float*)d_out;

    init_kernel<<<64, 256>>>(out);
    hist_kernel<<<NQ_TOT / 256, 256>>>(pts);
    scan_kernel<<<BATCH, SCAN_T>>>();
    scatter_kernel<<<NQ_TOT / 256, 256>>>(pts);
    knn_kernel<<<NQ_TOT / BLOCK, BLOCK>>>(out);
}